// round 17
// baseline (speedup 1.0000x reference)
#include <cuda_runtime.h>
#include <cuda_fp16.h>
#include <math_constants.h>
#include <limits.h>
#include <stdint.h>

#define NPTS 500000
#define BGR 64
#define DIN 64
#define DH 128
#define DO 128
#define TILE 256

// ---------------- device scratch ----------------
__device__ float g_cc[BGR][DH];
// paired fp16 weight fragments: uint4 = {j0.b0, j0.b1, j1.b0, j1.b1}
// layout: [kchunk][jpair][lane]
__device__ uint4 g_W1f4[4 * 8 * 32];
__device__ uint4 g_W2f4[8 * 8 * 32];

__device__ __forceinline__ void atomicMaxFloat(float* addr, float val) {
    if (val >= 0.0f) atomicMax((int*)addr, __float_as_int(val));
    else             atomicMin((unsigned int*)addr, __float_as_uint(val));
}

__device__ __forceinline__ uint32_t pk16(float a, float b) {
    __half2 t = __halves2half2(__float2half_rn(a), __float2half_rn(b));
    return *(uint32_t*)&t;
}

__device__ __forceinline__ void mma16816(float* c, const uint32_t* a, uint32_t b0, uint32_t b1) {
    asm volatile(
        "mma.sync.aligned.m16n8k16.row.col.f32.f16.f16.f32 "
        "{%0,%1,%2,%3}, {%4,%5,%6,%7}, {%8,%9}, {%0,%1,%2,%3};"
        : "+f"(c[0]), "+f"(c[1]), "+f"(c[2]), "+f"(c[3])
        : "r"(a[0]), "r"(a[1]), "r"(a[2]), "r"(a[3]), "r"(b0), "r"(b1));
}

// ---------------- k_graph: prep + per-graph COM/argmin/c_g/small outputs ----
__global__ __launch_bounds__(256) void k_graph(
    const float* __restrict__ x, const float* __restrict__ pos,
    const int* __restrict__ batch, const float* __restrict__ lf,
    const float* __restrict__ W1, const float* __restrict__ W2,
    const float* __restrict__ b1, float* out, int out_size) {

    const int g = blockIdx.x;
    const int tid = threadIdx.x;
    const int wid = tid >> 5, l = tid & 31;

    // ---- prep section (distributed across blocks) ----
    {
        int i = g * 256 + tid;   // 16384 threads
        int lim = (BGR * DO < out_size) ? BGR * DO : out_size;
        if (i < lim) out[i] = -CUDART_INF_F;

        if (i < 4 * 8 * 32) {    // W1x paired fragment: t(4), jp(8), l(32)
            int ll = i & 31, jp = (i >> 5) & 7, t = i >> 8;
            int n0 = 8 * (2 * jp)     + (ll >> 2);
            int n1 = 8 * (2 * jp + 1) + (ll >> 2);
            int k0 = 16 * t + 2 * (ll & 3);
            uint4 v;
            v.x = pk16(W1[(DIN + k0) * DH + n0],     W1[(DIN + k0 + 1) * DH + n0]);
            v.y = pk16(W1[(DIN + k0 + 8) * DH + n0], W1[(DIN + k0 + 9) * DH + n0]);
            v.z = pk16(W1[(DIN + k0) * DH + n1],     W1[(DIN + k0 + 1) * DH + n1]);
            v.w = pk16(W1[(DIN + k0 + 8) * DH + n1], W1[(DIN + k0 + 9) * DH + n1]);
            g_W1f4[i] = v;
        }
        if (i < 8 * 8 * 32) {    // W2 paired fragment: t(8), jp(8), l(32)
            int ll = i & 31, jp = (i >> 5) & 7, t = i >> 8;
            int n0 = 8 * (2 * jp)     + (ll >> 2);
            int n1 = 8 * (2 * jp + 1) + (ll >> 2);
            int k0 = 16 * t + 2 * (ll & 3);
            uint4 v;
            v.x = pk16(W2[k0 * DO + n0],       W2[(k0 + 1) * DO + n0]);
            v.y = pk16(W2[(k0 + 8) * DO + n0], W2[(k0 + 9) * DO + n0]);
            v.z = pk16(W2[k0 * DO + n1],       W2[(k0 + 1) * DO + n1]);
            v.w = pk16(W2[(k0 + 8) * DO + n1], W2[(k0 + 9) * DO + n1]);
            g_W2f4[i] = v;
        }
    }

    __shared__ int s_s, s_e;
    __shared__ float s_red[3][8];
    __shared__ float s_com[3];
    __shared__ unsigned long long s_best;
    __shared__ int s_idx;
    __shared__ float s_x[DIN];
    __shared__ float s_p[3];

    if (tid == 0) {
        int lo = 0, hi = NPTS;
        while (lo < hi) { int m = (lo + hi) >> 1; if (batch[m] < g) lo = m + 1; else hi = m; }
        s_s = lo;
        hi = NPTS;
        while (lo < hi) { int m = (lo + hi) >> 1; if (batch[m] <= g) lo = m + 1; else hi = m; }
        s_e = lo;
        s_best = ~0ull;
    }
    __syncthreads();
    const int s = s_s, e = s_e;

    // ---- phase A: COM ----
    float sx = 0.f, sy = 0.f, sz = 0.f;
    for (int i = s + tid; i < e; i += 256) {
        sx += pos[3 * i]; sy += pos[3 * i + 1]; sz += pos[3 * i + 2];
    }
    #pragma unroll
    for (int d = 16; d >= 1; d >>= 1) {
        sx += __shfl_xor_sync(0xffffffffu, sx, d);
        sy += __shfl_xor_sync(0xffffffffu, sy, d);
        sz += __shfl_xor_sync(0xffffffffu, sz, d);
    }
    if (l == 0) { s_red[0][wid] = sx; s_red[1][wid] = sy; s_red[2][wid] = sz; }
    __syncthreads();
    if (tid < 3) {
        float t = 0.f;
        #pragma unroll
        for (int w = 0; w < 8; w++) t += s_red[tid][w];
        float cnt = (float)(e - s);
        s_com[tid] = t / fmaxf(cnt, 1.0f);
    }
    __syncthreads();

    // ---- phase B: argmin dist (first occurrence) ----
    {
        const float cx = s_com[0], cy = s_com[1], cz = s_com[2];
        unsigned long long best = ~0ull;
        for (int i = s + tid; i < e; i += 256) {
            float dx = pos[3 * i] - cx, dy = pos[3 * i + 1] - cy, dz = pos[3 * i + 2] - cz;
            float d = sqrtf(dx * dx + dy * dy + dz * dz);
            unsigned long long key = ((unsigned long long)__float_as_uint(d) << 32) | (unsigned)i;
            if (key < best) best = key;
        }
        atomicMin(&s_best, best);
    }
    __syncthreads();
    if (tid == 0)
        s_idx = (e > s) ? (int)(unsigned)(s_best & 0xffffffffu) : (NPTS - 1);
    __syncthreads();
    const int idx = s_idx;
    if (tid < DIN) s_x[tid] = x[(size_t)idx * DIN + tid];
    if (tid < 3) s_p[tid] = pos[3 * idx + tid];
    __syncthreads();

    // ---- phase C: c_g + small outputs ----
    if (tid < DH) {
        int j = tid;
        float c = b1[j];
        #pragma unroll 8
        for (int k = 0; k < DIN; k++)
            c += s_x[k] * (W1[k * DH + j] - W1[(DIN + k) * DH + j]);
        c -= s_p[0] * W1[(2 * DIN) * DH + j] + s_p[1] * W1[(2 * DIN + 1) * DH + j]
           + s_p[2] * W1[(2 * DIN + 2) * DH + j];
        g_cc[g][j] = c;
        if (j < 3)  { int o = BGR * DO + g * 3 + j;               if (o < out_size) out[o] = s_p[j]; }
        if (j == 0) { int o = BGR * DO + BGR * 3 + g;             if (o < out_size) out[o] = (float)g; }
        if (j < 9)  { int o = BGR * DO + BGR * 3 + BGR + g*9 + j; if (o < out_size) out[o] = lf[(size_t)idx * 9 + j]; }
    }
}

// ---------------- main kernel: 128 thr, 4 warps x 64 rows, 2 CTAs/SM -------
__global__ void __launch_bounds__(128, 2) k_main(
    const float* __restrict__ x, const float* __restrict__ pos,
    const int* __restrict__ batch, const float* __restrict__ W1,
    const float* __restrict__ b2, float* __restrict__ out) {

    __shared__ float wpx[128], wpy[128], wpz[128];
    __shared__ float cgs[128], b2s[128];
    __shared__ float px[TILE], py[TILE], pz[TILE];
    __shared__ float red[4 * 128];
    __shared__ int gbs[TILE];

    const int tid = threadIdx.x;
    const int wid = tid >> 5, l = tid & 31;
    const int row0 = blockIdx.x * TILE;

    if (tid < 128) {
        wpx[tid] = W1[(2 * DIN + 0) * DH + tid];
        wpy[tid] = W1[(2 * DIN + 1) * DH + tid];
        wpz[tid] = W1[(2 * DIN + 2) * DH + tid];
        b2s[tid] = b2[tid];
    }
    #pragma unroll
    for (int tt = 0; tt < 2; tt++) {
        int t = tt * 128 + tid;
        int row = row0 + t;
        if (row < NPTS) {
            px[t] = pos[3 * row]; py[t] = pos[3 * row + 1]; pz[t] = pos[3 * row + 2];
            gbs[t] = batch[row];
        } else {
            px[t] = py[t] = pz[t] = 0.f;
            gbs[t] = -1;
        }
    }
    __syncthreads();
    const int gu = gbs[0];
    const bool uni = (gu >= 0) && (gu == gbs[TILE - 1]);
    cgs[tid] = (gu >= 0) ? g_cc[gu][tid] : 0.f;
    __syncthreads();

    const int q = l >> 2;
    const int m4 = 2 * (l & 3);

    // ---------- phase 1: m-tile pairs; B shared within pair ----------
    uint32_t ah[4][16][2];
    #pragma unroll
    for (int p = 0; p < 2; p++) {
        // x fragments for the two m-tiles of this pair
        uint32_t xh[2][4][4];
        #pragma unroll
        for (int mi = 0; mi < 2; mi++) {
            const int rr0 = wid * 64 + (2 * p + mi) * 16 + q;
            const int r0 = row0 + rr0, r1 = r0 + 8;
            #pragma unroll
            for (int t = 0; t < 4; t++) {
                const int kb = 16 * t + m4;
                float2 x00 = make_float2(0.f, 0.f), x01 = x00, x10 = x00, x11 = x00;
                if (r0 < NPTS) {
                    x00 = *(const float2*)(x + (size_t)r0 * DIN + kb);
                    x01 = *(const float2*)(x + (size_t)r0 * DIN + kb + 8);
                }
                if (r1 < NPTS) {
                    x10 = *(const float2*)(x + (size_t)r1 * DIN + kb);
                    x11 = *(const float2*)(x + (size_t)r1 * DIN + kb + 8);
                }
                xh[mi][t][0] = pk16(x00.x, x00.y); xh[mi][t][1] = pk16(x10.x, x10.y);
                xh[mi][t][2] = pk16(x01.x, x01.y); xh[mi][t][3] = pk16(x11.x, x11.y);
            }
        }

        #pragma unroll
        for (int hq = 0; hq < 4; hq++) {
            float acc1[2][4][4];
            #pragma unroll
            for (int mi = 0; mi < 2; mi++)
                #pragma unroll
                for (int j = 0; j < 4; j++)
                    #pragma unroll
                    for (int qq = 0; qq < 4; qq++) acc1[mi][j][qq] = 0.f;

            #pragma unroll
            for (int t = 0; t < 4; t++) {
                const uint4* wf = g_W1f4 + (t * 8 + hq * 2) * 32 + l;
                uint4 B0 = wf[0];
                uint4 B1 = wf[32];
                #pragma unroll
                for (int mi = 0; mi < 2; mi++) {
                    mma16816(acc1[mi][0], xh[mi][t], B0.x, B0.y);
                    mma16816(acc1[mi][1], xh[mi][t], B0.z, B0.w);
                    mma16816(acc1[mi][2], xh[mi][t], B1.x, B1.y);
                    mma16816(acc1[mi][3], xh[mi][t], B1.z, B1.w);
                }
            }

            // epilogue 1 for this quarter: LDS hoisted per j outside mi loop
            #pragma unroll
            for (int j = 0; j < 4; j++) {
                const int jj = hq * 4 + j;
                const int c0 = 8 * jj + m4;
                const float2 wx = *(float2*)&wpx[c0];
                const float2 wy = *(float2*)&wpy[c0];
                const float2 wz = *(float2*)&wpz[c0];
                const float2 cvu = *(float2*)&cgs[c0];
                #pragma unroll
                for (int mi = 0; mi < 2; mi++) {
                    const int mt = 2 * p + mi;
                    const int rr0 = wid * 64 + mt * 16 + q;
                    const int rr1 = rr0 + 8;
                    float2 cv0, cv1;
                    if (uni) { cv0 = cvu; cv1 = cvu; }
                    else {
                        int g0 = gbs[rr0], g1 = gbs[rr1];
                        cv0 = (g0 >= 0) ? *(const float2*)&g_cc[g0][c0] : make_float2(0.f, 0.f);
                        cv1 = (g1 >= 0) ? *(const float2*)&g_cc[g1][c0] : make_float2(0.f, 0.f);
                    }
                    const float p0x = px[rr0], p0y = py[rr0], p0z = pz[rr0];
                    const float p1x = px[rr1], p1y = py[rr1], p1z = pz[rr1];
                    float v0 = fmaxf(acc1[mi][j][0] + p0x * wx.x + p0y * wy.x + p0z * wz.x + cv0.x, 0.f);
                    float v1 = fmaxf(acc1[mi][j][1] + p0x * wx.y + p0y * wy.y + p0z * wz.y + cv0.y, 0.f);
                    float v2 = fmaxf(acc1[mi][j][2] + p1x * wx.x + p1y * wy.x + p1z * wz.x + cv1.x, 0.f);
                    float v3 = fmaxf(acc1[mi][j][3] + p1x * wx.y + p1y * wy.y + p1z * wz.y + cv1.y, 0.f);
                    ah[mt][jj][0] = pk16(v0, v1); ah[mt][jj][1] = pk16(v2, v3);
                }
            }
        }
    }

    // ---------- phase 2: col-quarters, B shared across ALL 4 m-tiles ----------
    #pragma unroll
    for (int hq = 0; hq < 4; hq++) {
        float acc2[4][4][4];
        #pragma unroll
        for (int mt = 0; mt < 4; mt++)
            #pragma unroll
            for (int j = 0; j < 4; j++)
                #pragma unroll
                for (int qq = 0; qq < 4; qq++) acc2[mt][j][qq] = 0.f;

        #pragma unroll
        for (int t = 0; t < 8; t++) {
            const uint4* wf = g_W2f4 + (t * 8 + hq * 2) * 32 + l;
            uint4 B0 = wf[0];
            uint4 B1 = wf[32];
            #pragma unroll
            for (int mt = 0; mt < 4; mt++) {
                uint32_t A[4] = { ah[mt][2 * t][0], ah[mt][2 * t][1],
                                  ah[mt][2 * t + 1][0], ah[mt][2 * t + 1][1] };
                mma16816(acc2[mt][0], A, B0.x, B0.y);
                mma16816(acc2[mt][1], A, B0.z, B0.w);
                mma16816(acc2[mt][2], A, B1.x, B1.y);
                mma16816(acc2[mt][3], A, B1.z, B1.w);
            }
        }

        // epilogue 2 for this quarter
        if (uni) {
            #pragma unroll
            for (int j = 0; j < 4; j++) {
                int c0 = 8 * (hq * 4 + j) + m4;
                float m0 = fmaxf(fmaxf(acc2[0][j][0], acc2[0][j][2]),
                                 fmaxf(acc2[1][j][0], acc2[1][j][2]));
                m0 = fmaxf(m0, fmaxf(fmaxf(acc2[2][j][0], acc2[2][j][2]),
                                     fmaxf(acc2[3][j][0], acc2[3][j][2])));
                float m1 = fmaxf(fmaxf(acc2[0][j][1], acc2[0][j][3]),
                                 fmaxf(acc2[1][j][1], acc2[1][j][3]));
                m1 = fmaxf(m1, fmaxf(fmaxf(acc2[2][j][1], acc2[2][j][3]),
                                     fmaxf(acc2[3][j][1], acc2[3][j][3])));
                #pragma unroll
                for (int d = 4; d < 32; d <<= 1) {
                    m0 = fmaxf(m0, __shfl_xor_sync(0xffffffffu, m0, d));
                    m1 = fmaxf(m1, __shfl_xor_sync(0xffffffffu, m1, d));
                }
                if (l < 4) {
                    red[wid * 128 + c0] = m0;
                    red[wid * 128 + c0 + 1] = m1;
                }
            }
        } else {
            #pragma unroll
            for (int mt = 0; mt < 4; mt++) {
                const int rr0 = wid * 64 + mt * 16 + q;
                const int g0 = gbs[rr0], g1 = gbs[rr0 + 8];
                #pragma unroll
                for (int j = 0; j < 4; j++) {
                    int c0 = 8 * (hq * 4 + j) + m4;
                    if (g0 >= 0) {
                        atomicMaxFloat(&out[g0 * DO + c0],     acc2[mt][j][0] + b2s[c0]);
                        atomicMaxFloat(&out[g0 * DO + c0 + 1], acc2[mt][j][1] + b2s[c0 + 1]);
                    }
                    if (g1 >= 0) {
                        atomicMaxFloat(&out[g1 * DO + c0],     acc2[mt][j][2] + b2s[c0]);
                        atomicMaxFloat(&out[g1 * DO + c0 + 1], acc2[mt][j][3] + b2s[c0 + 1]);
                    }
                }
            }
        }
    }

    if (uni) {
        __syncthreads();
        float m = red[tid];
        #pragma unroll
        for (int w = 1; w < 4; w++) m = fmaxf(m, red[w * 128 + tid]);
        atomicMaxFloat(&out[gu * DO + tid], m + b2s[tid]);
    }
}

// ---------------- launch ----------------
extern "C" void kernel_launch(void* const* d_in, const int* in_sizes, int n_in,
                              void* d_out, int out_size) {
    const float* x     = (const float*)d_in[0];
    const float* pos   = (const float*)d_in[1];
    const int*   batch = (const int*)d_in[2];
    const float* lf    = (const float*)d_in[3];
    const float* W1    = (const float*)d_in[4];
    const float* b1    = (const float*)d_in[5];
    const float* W2    = (const float*)d_in[6];
    const float* b2    = (const float*)d_in[7];
    float* out = (float*)d_out;

    k_graph<<<BGR, 256>>>(x, pos, batch, lf, W1, W2, b1, out, out_size);
    int grid = (NPTS + TILE - 1) / TILE;
    k_main<<<grid, 128>>>(x, pos, batch, W1, b2, out);
}